// round 1
// baseline (speedup 1.0000x reference)
#include <cuda_runtime.h>
#include <math_constants.h>

#define N 512
#define D 64
#define MAX_STEPS 10

// ---- persistent scratch (no allocations allowed) ----
__device__ float        g_p[N];
__device__ float        g_arr[N];
__device__ unsigned int g_cand[N];
__device__ float        g_rowconst[N * D];  // nf[i]@W1[0:64] + b1
__device__ float        g_Bt[D * N];        // (nf[j]@W1[64:128]) transposed: [k][j]
__device__ float        g_rowvec[N * D];    // per-step: rowconst + p*w129 + sf*w130
__device__ float        g_f0[N];            // node_features[:,0]

// ---------------------------------------------------------------------------
__global__ void k_init_state(const int* __restrict__ shock, int n_shock) {
    int t = threadIdx.x;
    if (t < N) { g_p[t] = 0.f; g_arr[t] = CUDART_INF_F; }
    __syncthreads();
    if (t < n_shock) { int s = shock[t]; g_p[s] = 1.f; g_arr[s] = 0.f; }
}

// 128 blocks x 256 = 32768 threads; each computes one elem of rowconst and Bt.
__global__ void k_init_ab(const float* __restrict__ nf,
                          const float* __restrict__ W1,
                          const float* __restrict__ b1) {
    int gid = blockIdx.x * 256 + threadIdx.x;     // < 32768
    int i = gid >> 6, k = gid & 63;
    float accA = b1[k];
#pragma unroll 8
    for (int d = 0; d < D; d++) accA = fmaf(nf[i * D + d], W1[d * D + k], accA);
    g_rowconst[gid] = accA;

    int j = gid & (N - 1), kk = gid >> 9;          // kk < 64
    float accB = 0.f;
#pragma unroll 8
    for (int d = 0; d < D; d++) accB = fmaf(nf[j * D + d], W1[(D + d) * D + kk], accB);
    g_Bt[kk * N + j] = accB;

    if (gid < N) g_f0[gid] = nf[gid * D];
}

// per step: rowvec = rowconst + p[i]*W1[129] + sf*W1[130]; also zero cand
__global__ void k_rowvec(const float* __restrict__ W1, float sf) {
    int gid = blockIdx.x * 256 + threadIdx.x;     // < 32768
    int i = gid >> 6, k = gid & 63;
    g_rowvec[gid] = fmaf(g_p[i], W1[129 * D + k],
                    fmaf(sf, W1[130 * D + k], g_rowconst[gid]));
    if (gid < N) g_cand[gid] = 0u;
}

// heavy kernel: block = 8 src rows x 32 targets; warp = one i, lane = one j
__global__ void __launch_bounds__(256)
k_edges(const float* __restrict__ cgm, const float* __restrict__ W1,
        const float* __restrict__ W2,  const float* __restrict__ b2,
        const float* __restrict__ W3,  const float* __restrict__ b3) {
    __shared__ float s_w2[D * 32];       // W2[k][m], broadcast reads
    __shared__ float s_bt[D * 32];       // Bt tile [k][lane], conflict-free
    __shared__ float s_rv[8 * D];        // rowvec tile
    __shared__ float s_w128[D], s_w131[D], s_w3[32], s_b2[32];
    __shared__ unsigned int s_cand[32];
    __shared__ float s_b3;
    __shared__ int s_alive;

    int tid = threadIdx.x;
    int warp = tid >> 5, lane = tid & 31;
    int j0 = blockIdx.x * 32;
    int i0 = blockIdx.y * 8;
    int i = i0 + warp;
    int j = j0 + lane;

    float p_i = g_p[i];
    if (tid == 0) s_alive = 0;
    __syncthreads();
    if (lane == 0 && p_i > 0.f) s_alive = 1;   // benign race
    __syncthreads();
    if (!s_alive) return;                      // whole block dead (step 0 mostly)

    for (int idx = tid; idx < D * 32; idx += 256) {
        s_w2[idx] = W2[idx];
        int kk = idx >> 5, jl = idx & 31;
        s_bt[idx] = g_Bt[kk * N + j0 + jl];
    }
    for (int idx = tid; idx < 8 * D; idx += 256) s_rv[idx] = g_rowvec[i0 * D + idx];
    if (tid < D) { s_w128[tid] = W1[128 * D + tid]; s_w131[tid] = W1[131 * D + tid]; }
    if (tid < 32) { s_w3[tid] = W3[tid]; s_b2[tid] = b2[tid]; s_cand[tid] = 0u; }
    if (tid == 0) s_b3 = b3[0];
    __syncthreads();

    float val = 0.f;
    if (p_i > 0.f) {
        float cg = cgm[i * N + j];
        float fd = fabsf(g_f0[i] - g_f0[j]);
        float h2[32];
#pragma unroll
        for (int m = 0; m < 32; m++) h2[m] = s_b2[m];
        const float* rv = &s_rv[warp * D];
#pragma unroll 4
        for (int k = 0; k < D; k++) {
            float h1 = fmaf(cg, s_w128[k], rv[k] + s_bt[(k << 5) + lane]);
            h1 = fmaf(fd, s_w131[k], h1);
            h1 = fmaxf(h1, 0.f);
#pragma unroll
            for (int m = 0; m < 32; m++)
                h2[m] = fmaf(h1, s_w2[(k << 5) + m], h2[m]);
        }
        float z = s_b3;
#pragma unroll
        for (int m = 0; m < 32; m++) z = fmaf(fmaxf(h2[m], 0.f), s_w3[m], z);
        float t = 1.f / (1.f + __expf(-z));
        if (cg > 0.f) val = p_i * t * cg;      // active mask
    }
    // val >= 0 always -> uint compare == float compare
    if (val > 0.f) atomicMax(&s_cand[lane], __float_as_uint(val));
    __syncthreads();
    if (tid < 32) {
        unsigned v = s_cand[tid];
        if (v) atomicMax(&g_cand[j0 + tid], v);
    }
}

__global__ void k_update(float step_plus1, float* __restrict__ out) {
    int j = blockIdx.x * 256 + threadIdx.x;
    if (j >= N) return;
    float cand = __uint_as_float(g_cand[j]);
    float p = g_p[j], a = g_arr[j];
    if (cand > p) { p = cand; a = fminf(a, step_plus1); }
    g_p[j] = p; g_arr[j] = a;
    out[j] = p; out[N + j] = a;                // final step leaves the answer
}

// ---------------------------------------------------------------------------
extern "C" void kernel_launch(void* const* d_in, const int* in_sizes, int n_in,
                              void* d_out, int out_size) {
    const float* cg    = (const float*)d_in[0];
    const float* nf    = (const float*)d_in[1];
    const int*   shock = (const int*)  d_in[2];
    const float* W1    = (const float*)d_in[3];
    const float* b1    = (const float*)d_in[4];
    const float* W2    = (const float*)d_in[5];
    const float* b2    = (const float*)d_in[6];
    const float* W3    = (const float*)d_in[7];
    const float* b3    = (const float*)d_in[8];
    float* out = (float*)d_out;

    k_init_state<<<1, 512>>>(shock, in_sizes[2]);
    k_init_ab<<<128, 256>>>(nf, W1, b1);
    for (int s = 0; s < MAX_STEPS; s++) {
        k_rowvec<<<128, 256>>>(W1, (float)s / (float)MAX_STEPS);
        k_edges<<<dim3(16, 64), 256>>>(cg, W1, W2, b2, W3, b3);
        k_update<<<2, 256>>>((float)(s + 1), out);
    }
}

// round 2
// speedup vs baseline: 1.0674x; 1.0674x over previous
#include <cuda_runtime.h>
#include <math_constants.h>

#define N 512
#define D 64
#define MAX_STEPS 10

// ---- persistent scratch (no allocations allowed) ----
__device__ float        g_p[N];
__device__ float        g_arr[N];
__device__ unsigned int g_cand[N];
__device__ float        g_rowconst[N * D];  // nf[i]@W1[0:64] + b1
__device__ float        g_Bt[D * N];        // (nf[j]@W1[64:128]) transposed: [k][j]
__device__ float        g_f0[N];            // node_features[:,0]

// ---------------------------------------------------------------------------
__global__ void k_init_state(const int* __restrict__ shock, int n_shock) {
    int t = threadIdx.x;
    if (t < N) { g_p[t] = 0.f; g_arr[t] = CUDART_INF_F; g_cand[t] = 0u; }
    __syncthreads();
    if (t < n_shock) { int s = shock[t]; g_p[s] = 1.f; g_arr[s] = 0.f; }
}

// 128 blocks x 256 = 32768 threads; each computes one elem of rowconst and Bt.
__global__ void k_init_ab(const float* __restrict__ nf,
                          const float* __restrict__ W1,
                          const float* __restrict__ b1) {
    int gid = blockIdx.x * 256 + threadIdx.x;     // < 32768
    int i = gid >> 6, k = gid & 63;
    float accA = b1[k];
#pragma unroll 8
    for (int d = 0; d < D; d++) accA = fmaf(nf[i * D + d], W1[d * D + k], accA);
    g_rowconst[gid] = accA;

    int j = gid & (N - 1), kk = gid >> 9;          // kk < 64
    float accB = 0.f;
#pragma unroll 8
    for (int d = 0; d < D; d++) accB = fmaf(nf[j * D + d], W1[(D + d) * D + kk], accB);
    g_Bt[kk * N + j] = accB;

    if (gid < N) g_f0[gid] = nf[gid * D];
}

// heavy kernel: block = 8 src rows x 32 targets; warp = one i, lane = one j
__global__ void __launch_bounds__(256)
k_edges(const float* __restrict__ cgm, const float* __restrict__ W1,
        const float* __restrict__ W2,  const float* __restrict__ b2,
        const float* __restrict__ W3,  const float* __restrict__ b3,
        float sf) {
    __shared__ __align__(16) float s_w2[D * 32];   // W2[k][m]
    __shared__ float s_bt[D * 32];                 // Bt tile [k][lane]
    __shared__ float s_rv[8 * D];                  // per-(row,k): rowconst + p*w129 + sf*w130
    __shared__ float2 s_wp[D];                     // (w128[k], w131[k])
    __shared__ float s_w3[32];
    __shared__ unsigned long long s_b2p[16];       // b2 packed in pairs
    __shared__ unsigned int s_cand[32];
    __shared__ float s_b3;
    __shared__ int s_alive;

    int tid = threadIdx.x;
    int warp = tid >> 5, lane = tid & 31;
    int j0 = blockIdx.x * 32;
    int i0 = blockIdx.y * 8;
    int i = i0 + warp;
    int j = j0 + lane;

    float p_i = g_p[i];
    if (tid == 0) s_alive = 0;
    __syncthreads();
    if (lane == 0 && p_i > 0.f) s_alive = 1;   // benign race
    __syncthreads();
    if (!s_alive) return;                      // whole block dead (step 0 mostly)

    for (int idx = tid; idx < D * 32; idx += 256) {
        s_w2[idx] = W2[idx];
        int kk = idx >> 5, jl = idx & 31;
        s_bt[idx] = g_Bt[kk * N + j0 + jl];
    }
    for (int idx = tid; idx < 8 * D; idx += 256) {
        int row = idx >> 6, k = idx & 63;
        s_rv[idx] = fmaf(g_p[i0 + row], W1[129 * D + k],
                    fmaf(sf, W1[130 * D + k], g_rowconst[(i0 + row) * D + k]));
    }
    if (tid < D) s_wp[tid] = make_float2(W1[128 * D + tid], W1[131 * D + tid]);
    if (tid < 32) { s_w3[tid] = W3[tid]; s_cand[tid] = 0u; }
    if (tid < 16) {
        unsigned long long pk;
        asm("mov.b64 %0, {%1, %2};" : "=l"(pk) : "f"(b2[2 * tid]), "f"(b2[2 * tid + 1]));
        s_b2p[tid] = pk;
    }
    if (tid == 0) s_b3 = b3[0];
    __syncthreads();

    float val = 0.f;
    if (p_i > 0.f) {
        float cg = cgm[i * N + j];
        float fd = fabsf(g_f0[i] - g_f0[j]);
        unsigned long long h2[16];
#pragma unroll
        for (int q = 0; q < 16; q++) h2[q] = s_b2p[q];
        const float* rv = &s_rv[warp * D];
#pragma unroll 4
        for (int k = 0; k < D; k++) {
            float2 wp = s_wp[k];
            float h1 = rv[k] + s_bt[(k << 5) + lane];
            h1 = fmaf(cg, wp.x, h1);
            h1 = fmaf(fd, wp.y, h1);
            h1 = fmaxf(h1, 0.f);
            unsigned long long h1x2;
            asm("mov.b64 %0, {%1, %1};" : "=l"(h1x2) : "f"(h1));
            const ulonglong2* w2p = reinterpret_cast<const ulonglong2*>(&s_w2[k << 5]);
#pragma unroll
            for (int q = 0; q < 8; q++) {
                ulonglong2 v = w2p[q];   // LDS.128: two packed f32 pairs
                asm("fma.rn.f32x2 %0, %1, %2, %0;"
                    : "+l"(h2[2 * q])     : "l"(h1x2), "l"(v.x));
                asm("fma.rn.f32x2 %0, %1, %2, %0;"
                    : "+l"(h2[2 * q + 1]) : "l"(h1x2), "l"(v.y));
            }
        }
        float z = s_b3;
#pragma unroll
        for (int q = 0; q < 16; q++) {
            float lo, hi;
            asm("mov.b64 {%0, %1}, %2;" : "=f"(lo), "=f"(hi) : "l"(h2[q]));
            z = fmaf(fmaxf(lo, 0.f), s_w3[2 * q], z);
            z = fmaf(fmaxf(hi, 0.f), s_w3[2 * q + 1], z);
        }
        float t = 1.f / (1.f + __expf(-z));
        if (cg > 0.f) val = p_i * t * cg;      // active mask
    }
    // val >= 0 always -> uint compare == float compare
    if (val > 0.f) atomicMax(&s_cand[lane], __float_as_uint(val));
    __syncthreads();
    if (tid < 32) {
        unsigned v = s_cand[tid];
        if (v) atomicMax(&g_cand[j0 + tid], v);
    }
}

// reads cand, updates p/arr, zeroes cand for the next step, writes out
__global__ void k_update(float step_plus1, float* __restrict__ out) {
    int j = blockIdx.x * 256 + threadIdx.x;
    if (j >= N) return;
    float cand = __uint_as_float(g_cand[j]);
    g_cand[j] = 0u;
    float p = g_p[j], a = g_arr[j];
    if (cand > p) { p = cand; a = fminf(a, step_plus1); }
    g_p[j] = p; g_arr[j] = a;
    out[j] = p; out[N + j] = a;                // final step leaves the answer
}

// ---------------------------------------------------------------------------
extern "C" void kernel_launch(void* const* d_in, const int* in_sizes, int n_in,
                              void* d_out, int out_size) {
    const float* cg    = (const float*)d_in[0];
    const float* nf    = (const float*)d_in[1];
    const int*   shock = (const int*)  d_in[2];
    const float* W1    = (const float*)d_in[3];
    const float* b1    = (const float*)d_in[4];
    const float* W2    = (const float*)d_in[5];
    const float* b2    = (const float*)d_in[6];
    const float* W3    = (const float*)d_in[7];
    const float* b3    = (const float*)d_in[8];
    float* out = (float*)d_out;

    k_init_state<<<1, 512>>>(shock, in_sizes[2]);
    k_init_ab<<<128, 256>>>(nf, W1, b1);
    for (int s = 0; s < MAX_STEPS; s++) {
        k_edges<<<dim3(16, 64), 256>>>(cg, W1, W2, b2, W3, b3,
                                       (float)s / (float)MAX_STEPS);
        k_update<<<2, 256>>>((float)(s + 1), out);
    }
}